// round 2
// baseline (speedup 1.0000x reference)
#include <cuda_runtime.h>
#include <stdint.h>

#define N_VOX        200000
#define N_COLS       5
#define N_CLUSTS     1024
#define PTS_PER      128
#define N_EDGES      8192

// Scratch: gathered cluster points, padded to float4 for coalesced/vector access.
__device__ float4 g_pts[N_CLUSTS * PTS_PER];

// -------------------------------------------------------------------------
// Kernel 1: gather voxels[clusts] -> g_pts  (131072 gathers, one-shot)
// -------------------------------------------------------------------------
__global__ void gather_pts_kernel(const float* __restrict__ data,
                                  const int* __restrict__ clusts) {
    int i = blockIdx.x * blockDim.x + threadIdx.x;   // 0 .. 1024*128-1
    if (i >= N_CLUSTS * PTS_PER) return;
    int idx = clusts[i];
    const float* p = data + (size_t)idx * N_COLS + 1;   // cols 1..3
    g_pts[i] = make_float4(p[0], p[1], p[2], 0.0f);
}

// -------------------------------------------------------------------------
// Kernel 2: one CTA per edge. 256 threads; thread (ti,tj) with ti=t>>4,
// tj=t&15 owns i1 in [8*ti, 8*ti+8) and i2 in {tj, tj+16, ..., tj+112}.
// The strided i2 ownership keeps float4 LDS accesses ~conflict-free.
// -------------------------------------------------------------------------
__global__ __launch_bounds__(256, 4)
void edge_feats_kernel(const int* __restrict__ edge_index,
                       float* __restrict__ out) {
    __shared__ float4 s1[PTS_PER];
    __shared__ float4 s2[PTS_PER];
    __shared__ unsigned long long s_best;

    const int e = blockIdx.x;
    const int t = threadIdx.x;

    const int c1 = edge_index[e];
    const int c2 = edge_index[N_EDGES + e];

    if (t == 0) s_best = 0xFFFFFFFFFFFFFFFFull;
    if (t < 128) {
        s1[t] = g_pts[c1 * PTS_PER + t];
    } else {
        int k = t - 128;
        s2[k] = g_pts[c2 * PTS_PER + k];
    }
    __syncthreads();

    const int ti = t >> 4;       // 0..15 -> i1 block
    const int tj = t & 15;       // 0..15 -> i2 lane

    // Load this thread's 8 x1 points into registers.
    float x1x[8], x1y[8], x1z[8];
#pragma unroll
    for (int a = 0; a < 8; a++) {
        float4 v = s1[ti * 8 + a];
        x1x[a] = v.x; x1y[a] = v.y; x1z[a] = v.z;
    }

    // Per-row best (row = i1). j stored as loop index b (i2 = 16*b + tj).
    float bestd[8];
    int   bestb[8];
#pragma unroll
    for (int a = 0; a < 8; a++) { bestd[a] = __int_as_float(0x7F800000); bestb[a] = 0; }

#pragma unroll
    for (int b = 0; b < 8; b++) {
        float4 v = s2[b * 16 + tj];
#pragma unroll
        for (int a = 0; a < 8; a++) {
            float dx = x1x[a] - v.x;
            float dy = x1y[a] - v.y;
            float dz = x1z[a] - v.z;
            float d2 = fmaf(dz, dz, fmaf(dy, dy, dx * dx));
            // ascending i2 within the row -> strict < keeps first occurrence
            if (d2 < bestd[a]) { bestd[a] = d2; bestb[a] = b; }
        }
    }

    // Merge rows (ascending i1 -> strict < keeps smaller flat index on ties).
    float bd = bestd[0];
    int   ba = 0, bb = bestb[0];
#pragma unroll
    for (int a = 1; a < 8; a++) {
        if (bestd[a] < bd) { bd = bestd[a]; ba = a; bb = bestb[a]; }
    }
    const int i1 = ti * 8 + ba;
    const int i2 = bb * 16 + tj;
    const int flat = i1 * PTS_PER + i2;

    // Pack (d2, flat) so uint64 min == lexicographic (d2, flat) min.
    // d2 >= 0 so float bits are monotone.
    unsigned long long key =
        ((unsigned long long)__float_as_uint(bd) << 32) | (unsigned int)flat;

    // Warp reduction then shared atomicMin.
#pragma unroll
    for (int off = 16; off > 0; off >>= 1) {
        unsigned long long o = __shfl_down_sync(0xFFFFFFFFu, key, off);
        key = (o < key) ? o : key;
    }
    if ((t & 31) == 0) atomicMin(&s_best, key);
    __syncthreads();

    if (t == 0) {
        unsigned long long k = s_best;
        int f  = (int)(k & 0xFFFFFFFFu);
        int w1 = f >> 7;
        int w2 = f & 127;
        float4 v1 = s1[w1];
        float4 v2 = s2[w2];

        float dx = v1.x - v2.x;
        float dy = v1.y - v2.y;
        float dz = v1.z - v2.z;
        float lend = sqrtf(fmaf(dz, dz, fmaf(dy, dy, dx * dx)));
        float nx, ny, nz;
        if (lend > 0.0f) {
            nx = dx / lend; ny = dy / lend; nz = dz / lend;
        } else {
            nx = dx; ny = dy; nz = dz;   // disp is all-zero here
        }

        float B[9];
        B[0] = nx * nx; B[1] = nx * ny; B[2] = nx * nz;
        B[3] = ny * nx; B[4] = ny * ny; B[5] = ny * nz;
        B[6] = nz * nx; B[7] = nz * ny; B[8] = nz * nz;

        float* o1 = out + (size_t)e * 38;   // row 2e
        float* o2 = o1 + 19;                // row 2e+1

        o1[0] = v1.x; o1[1] = v1.y; o1[2] = v1.z;
        o1[3] = v2.x; o1[4] = v2.y; o1[5] = v2.z;
        o1[6] = nx;   o1[7] = ny;   o1[8] = nz;
        o1[9] = lend;
#pragma unroll
        for (int q = 0; q < 9; q++) o1[10 + q] = B[q];

        o2[0] = v2.x; o2[1] = v2.y; o2[2] = v2.z;
        o2[3] = v1.x; o2[4] = v1.y; o2[5] = v1.z;
        o2[6] = -nx;  o2[7] = -ny;  o2[8] = -nz;
        o2[9] = lend;
#pragma unroll
        for (int q = 0; q < 9; q++) o2[10 + q] = B[q];
    }
}

// -------------------------------------------------------------------------
extern "C" void kernel_launch(void* const* d_in, const int* in_sizes, int n_in,
                              void* d_out, int out_size) {
    const float* data       = (const float*)d_in[0];   // [200000, 5] f32
    const int*   clusts     = (const int*)d_in[1];     // [1024, 128] i32
    const int*   edge_index = (const int*)d_in[2];     // [2, 8192] i32
    float*       out        = (float*)d_out;           // [16384, 19] f32

    gather_pts_kernel<<<(N_CLUSTS * PTS_PER + 255) / 256, 256>>>(data, clusts);
    edge_feats_kernel<<<N_EDGES, 256>>>(edge_index, out);
}

// round 3
// speedup vs baseline: 1.1230x; 1.1230x over previous
#include <cuda_runtime.h>
#include <stdint.h>

#define N_VOX        200000
#define N_COLS       5
#define N_CLUSTS     1024
#define PTS_PER      128
#define N_EDGES      8192

// Scratch: gathered cluster points, padded to float4.
__device__ float4 g_pts[N_CLUSTS * PTS_PER];

typedef unsigned long long ull;

// ---- packed f32x2 helpers (sm_103a FFMA2/FADD2 path, PTX-only) ----
__device__ __forceinline__ ull pack2(float lo, float hi) {
    ull r; asm("mov.b64 %0, {%1,%2};" : "=l"(r) : "f"(lo), "f"(hi)); return r;
}
__device__ __forceinline__ void unpack2(ull v, float& lo, float& hi) {
    asm("mov.b64 {%0,%1}, %2;" : "=f"(lo), "=f"(hi) : "l"(v));
}
__device__ __forceinline__ ull add2(ull a, ull b) {
    ull r; asm("add.rn.f32x2 %0, %1, %2;" : "=l"(r) : "l"(a), "l"(b)); return r;
}
__device__ __forceinline__ ull mul2(ull a, ull b) {
    ull r; asm("mul.rn.f32x2 %0, %1, %2;" : "=l"(r) : "l"(a), "l"(b)); return r;
}
__device__ __forceinline__ ull fma2(ull a, ull b, ull c) {
    ull r; asm("fma.rn.f32x2 %0, %1, %2, %3;" : "=l"(r) : "l"(a), "l"(b), "l"(c)); return r;
}

// -------------------------------------------------------------------------
// Kernel 1: gather voxels[clusts] -> g_pts
// -------------------------------------------------------------------------
__global__ void gather_pts_kernel(const float* __restrict__ data,
                                  const int* __restrict__ clusts) {
    int i = blockIdx.x * blockDim.x + threadIdx.x;
    if (i >= N_CLUSTS * PTS_PER) return;
    int idx = clusts[i];
    const float* p = data + (size_t)idx * N_COLS + 1;
    g_pts[i] = make_float4(p[0], p[1], p[2], 0.0f);
}

// -------------------------------------------------------------------------
// Kernel 2: one CTA per edge. 256 threads.
// Thread (ti, tj): ti = t>>4 owns i1 in [8*ti, 8*ti+8);
//                  tj = t&15 owns i2 packs k = tj + 16*b (b=0..3),
//                  each pack = points {2k, 2k+1}  -> 8 i2 points / thread.
// s2 holds NEGATED, f32x2-packed x2 coordinates so dx = x1 + s2 (one ADD2).
// -------------------------------------------------------------------------
__global__ __launch_bounds__(256, 4)
void edge_feats_kernel(const int* __restrict__ edge_index,
                       float* __restrict__ out) {
    __shared__ float4 s1[PTS_PER];
    __shared__ ull s2x[64], s2y[64], s2z[64];
    __shared__ ull s_best;

    const int e = blockIdx.x;
    const int t = threadIdx.x;

    const int c1 = edge_index[e];
    const int c2 = edge_index[N_EDGES + e];

    if (t == 0) s_best = 0xFFFFFFFFFFFFFFFFull;

    if (t < 128) {
        s1[t] = g_pts[c1 * PTS_PER + t];
    } else if (t < 192) {
        int k = t - 128;                     // 0..63
        float4 a = g_pts[c2 * PTS_PER + 2 * k];
        float4 b = g_pts[c2 * PTS_PER + 2 * k + 1];
        s2x[k] = pack2(-a.x, -b.x);
        s2y[k] = pack2(-a.y, -b.y);
        s2z[k] = pack2(-a.z, -b.z);
    }
    __syncthreads();

    const int ti = t >> 4;
    const int tj = t & 15;
    const int i1base = ti * 8;

    // Hoist this thread's 4 negated-v2 packs (conflict-free LDS.64).
    ull vx[4], vy[4], vz[4];
#pragma unroll
    for (int b = 0; b < 4; b++) {
        vx[b] = s2x[tj + 16 * b];
        vy[b] = s2y[tj + 16 * b];
        vz[b] = s2z[tj + 16 * b];
    }

    float bd = __int_as_float(0x7F800000);   // +inf
    int bidx = 0;

#pragma unroll
    for (int a = 0; a < 8; a++) {
        float4 p = s1[i1base + a];
        ull px = pack2(p.x, p.x);
        ull py = pack2(p.y, p.y);
        ull pz = pack2(p.z, p.z);

        ull d2p[4];
#pragma unroll
        for (int b = 0; b < 4; b++) {
            ull dx = add2(px, vx[b]);
            ull dy = add2(py, vy[b]);
            ull dz = add2(pz, vz[b]);
            d2p[b] = fma2(dz, dz, fma2(dy, dy, mul2(dx, dx)));
        }

        float h[8];
#pragma unroll
        for (int b = 0; b < 4; b++) unpack2(d2p[b], h[2 * b], h[2 * b + 1]);

        // balanced min tree
        float m01 = fminf(h[0], h[1]);
        float m23 = fminf(h[2], h[3]);
        float m45 = fminf(h[4], h[5]);
        float m67 = fminf(h[6], h[7]);
        float m = fminf(fminf(m01, m23), fminf(m45, m67));

        if (m < bd) {
            // rare slow path: scan in ascending-flat order, strict < keeps
            // first occurrence (matches jnp.argmin semantics exactly).
#pragma unroll
            for (int q = 0; q < 8; q++) {
                int b = q >> 1, half = q & 1;
                int flat = (i1base + a) * PTS_PER + 2 * tj + 32 * b + half;
                if (h[q] < bd) { bd = h[q]; bidx = flat; }
            }
        }
    }

    // Pack (d2, flat): uint64 min == lexicographic (d2, flat) min (d2 >= 0).
    ull key = ((ull)__float_as_uint(bd) << 32) | (unsigned int)bidx;

#pragma unroll
    for (int off = 16; off > 0; off >>= 1) {
        ull o = __shfl_down_sync(0xFFFFFFFFu, key, off);
        key = (o < key) ? o : key;
    }
    if ((t & 31) == 0) atomicMin(&s_best, key);
    __syncthreads();

    if (t == 0) {
        ull k = s_best;
        int f  = (int)(k & 0xFFFFFFFFu);
        int w1 = f >> 7;
        int w2 = f & 127;
        float4 v1 = s1[w1];
        float4 v2 = g_pts[c2 * PTS_PER + w2];

        float dx = v1.x - v2.x;
        float dy = v1.y - v2.y;
        float dz = v1.z - v2.z;
        float lend = sqrtf(fmaf(dz, dz, fmaf(dy, dy, dx * dx)));
        float nx, ny, nz;
        if (lend > 0.0f) {
            nx = dx / lend; ny = dy / lend; nz = dz / lend;
        } else {
            nx = dx; ny = dy; nz = dz;
        }

        float B[9];
        B[0] = nx * nx; B[1] = nx * ny; B[2] = nx * nz;
        B[3] = ny * nx; B[4] = ny * ny; B[5] = ny * nz;
        B[6] = nz * nx; B[7] = nz * ny; B[8] = nz * nz;

        float* o1 = out + (size_t)e * 38;
        float* o2 = o1 + 19;

        o1[0] = v1.x; o1[1] = v1.y; o1[2] = v1.z;
        o1[3] = v2.x; o1[4] = v2.y; o1[5] = v2.z;
        o1[6] = nx;   o1[7] = ny;   o1[8] = nz;
        o1[9] = lend;
#pragma unroll
        for (int q = 0; q < 9; q++) o1[10 + q] = B[q];

        o2[0] = v2.x; o2[1] = v2.y; o2[2] = v2.z;
        o2[3] = v1.x; o2[4] = v1.y; o2[5] = v1.z;
        o2[6] = -nx;  o2[7] = -ny;  o2[8] = -nz;
        o2[9] = lend;
#pragma unroll
        for (int q = 0; q < 9; q++) o2[10 + q] = B[q];
    }
}

// -------------------------------------------------------------------------
extern "C" void kernel_launch(void* const* d_in, const int* in_sizes, int n_in,
                              void* d_out, int out_size) {
    const float* data       = (const float*)d_in[0];   // [200000, 5] f32
    const int*   clusts     = (const int*)d_in[1];     // [1024, 128] i32
    const int*   edge_index = (const int*)d_in[2];     // [2, 8192] i32
    float*       out        = (float*)d_out;           // [16384, 19] f32

    gather_pts_kernel<<<(N_CLUSTS * PTS_PER + 255) / 256, 256>>>(data, clusts);
    edge_feats_kernel<<<N_EDGES, 256>>>(edge_index, out);
}

// round 5
// speedup vs baseline: 1.3155x; 1.1715x over previous
#include <cuda_runtime.h>
#include <stdint.h>

#define N_VOX        200000
#define N_COLS       5
#define N_CLUSTS     1024
#define PTS_PER      128
#define N_EDGES      8192

// Scratch: gathered cluster points, padded to float4.
__device__ float4 g_pts[N_CLUSTS * PTS_PER];

typedef unsigned long long ull;

// ---- packed f32x2 helpers (sm_103a FFMA2 path, PTX-only) ----
__device__ __forceinline__ ull pack2(float lo, float hi) {
    ull r; asm("mov.b64 %0, {%1,%2};" : "=l"(r) : "f"(lo), "f"(hi)); return r;
}
__device__ __forceinline__ void unpack2(ull v, float& lo, float& hi) {
    asm("mov.b64 {%0,%1}, %2;" : "=f"(lo), "=f"(hi) : "l"(v));
}
__device__ __forceinline__ ull add2(ull a, ull b) {
    ull r; asm("add.rn.f32x2 %0, %1, %2;" : "=l"(r) : "l"(a), "l"(b)); return r;
}
__device__ __forceinline__ ull mul2(ull a, ull b) {
    ull r; asm("mul.rn.f32x2 %0, %1, %2;" : "=l"(r) : "l"(a), "l"(b)); return r;
}
__device__ __forceinline__ ull fma2(ull a, ull b, ull c) {
    ull r; asm("fma.rn.f32x2 %0, %1, %2, %3;" : "=l"(r) : "l"(a), "l"(b), "l"(c)); return r;
}

// -------------------------------------------------------------------------
// Kernel 1: gather voxels[clusts] -> g_pts
// -------------------------------------------------------------------------
__global__ void gather_pts_kernel(const float* __restrict__ data,
                                  const int* __restrict__ clusts) {
    int i = blockIdx.x * blockDim.x + threadIdx.x;
    if (i >= N_CLUSTS * PTS_PER) return;
    int idx = clusts[i];
    const float* p = data + (size_t)idx * N_COLS + 1;
    g_pts[i] = make_float4(p[0], p[1], p[2], 0.0f);
}

// -------------------------------------------------------------------------
// Kernel 2: one CTA per edge. 256 threads.
// Thread (ti, tj): ti = t>>4 owns i1 rows [8*ti, 8*ti+8);
//                  tj = t&15 owns i2 packs k = tj + 16*b (b=0..3),
//                  pack k = points {2k, 2k+1}  -> 8 i2 points / thread.
// s1 coords stored DUPLICATE-PACKED (x,x) so the hot loop is 3 LDS.64, no MOVs.
// s2 coords stored NEGATED-PACKED so dx = x1 + s2 is a single ADD2.
// -------------------------------------------------------------------------
__global__ __launch_bounds__(256, 4)
void edge_feats_kernel(const int* __restrict__ edge_index,
                       float* __restrict__ out) {
    __shared__ ull s1x[PTS_PER], s1y[PTS_PER], s1z[PTS_PER];
    __shared__ ull s2x[64], s2y[64], s2z[64];
    __shared__ ull s_best;

    const int e = blockIdx.x;
    const int t = threadIdx.x;

    const int c1 = edge_index[e];
    const int c2 = edge_index[N_EDGES + e];

    if (t == 0) s_best = 0xFFFFFFFFFFFFFFFFull;

    if (t < 128) {
        float4 p = g_pts[c1 * PTS_PER + t];
        s1x[t] = pack2(p.x, p.x);
        s1y[t] = pack2(p.y, p.y);
        s1z[t] = pack2(p.z, p.z);
    } else if (t < 192) {
        int k = t - 128;                     // 0..63
        float4 a = g_pts[c2 * PTS_PER + 2 * k];
        float4 b = g_pts[c2 * PTS_PER + 2 * k + 1];
        s2x[k] = pack2(-a.x, -b.x);
        s2y[k] = pack2(-a.y, -b.y);
        s2z[k] = pack2(-a.z, -b.z);
    }
    __syncthreads();

    const int ti = t >> 4;
    const int tj = t & 15;
    const int i1base = ti * 8;

    // Hoist this thread's 4 negated-v2 packs (conflict-free LDS.64).
    ull vx[4], vy[4], vz[4];
#pragma unroll
    for (int b = 0; b < 4; b++) {
        vx[b] = s2x[tj + 16 * b];
        vy[b] = s2y[tj + 16 * b];
        vz[b] = s2z[tj + 16 * b];
    }

    float bd = __int_as_float(0x7F800000);   // +inf
    int besta = 0;

    // ---- hot loop: distances + row-min only (no index tracking) ----
#pragma unroll
    for (int a = 0; a < 8; a++) {
        ull px = s1x[i1base + a];
        ull py = s1y[i1base + a];
        ull pz = s1z[i1base + a];

        float h[8];
#pragma unroll
        for (int b = 0; b < 4; b++) {
            ull dx = add2(px, vx[b]);
            ull dy = add2(py, vy[b]);
            ull dz = add2(pz, vz[b]);
            ull d2 = fma2(dz, dz, fma2(dy, dy, mul2(dx, dx)));
            unpack2(d2, h[2 * b], h[2 * b + 1]);
        }

        float m01 = fminf(h[0], h[1]);
        float m23 = fminf(h[2], h[3]);
        float m45 = fminf(h[4], h[5]);
        float m67 = fminf(h[6], h[7]);
        float m = fminf(fminf(m01, m23), fminf(m45, m67));

        // Last strict improvement == first row attaining the final min.
        bool imp = (m < bd);
        bd = imp ? m : bd;
        besta = imp ? a : besta;
    }

    // ---- one-shot index recovery: recompute row `besta` (identical math) ----
    {
        ull px = s1x[i1base + besta];
        ull py = s1y[i1base + besta];
        ull pz = s1z[i1base + besta];

        float h[8];
#pragma unroll
        for (int b = 0; b < 4; b++) {
            ull dx = add2(px, vx[b]);
            ull dy = add2(py, vy[b]);
            ull dz = add2(pz, vz[b]);
            ull d2 = fma2(dz, dz, fma2(dy, dy, mul2(dx, dx)));
            unpack2(d2, h[2 * b], h[2 * b + 1]);
        }

        float cur = __int_as_float(0x7F800000);
        int bidx = 0;
        const int rowbase = (i1base + besta) * PTS_PER + 2 * tj;
#pragma unroll
        for (int q = 0; q < 8; q++) {
            int flat = rowbase + 32 * (q >> 1) + (q & 1);
            if (h[q] < cur) { cur = h[q]; bidx = flat; }   // ascending flat, strict <
        }

        // Pack (d2, flat): uint64 min == lexicographic min (d2 >= 0).
        ull key = ((ull)__float_as_uint(cur) << 32) | (unsigned int)bidx;

#pragma unroll
        for (int off = 16; off > 0; off >>= 1) {
            ull o = __shfl_down_sync(0xFFFFFFFFu, key, off);
            key = (o < key) ? o : key;
        }
        if ((t & 31) == 0) atomicMin(&s_best, key);
    }
    __syncthreads();

    if (t == 0) {
        ull k = s_best;
        int f  = (int)(k & 0xFFFFFFFFu);
        int w1 = f >> 7;
        int w2 = f & 127;

        float v1x, v1y, v1z, dummy;
        unpack2(s1x[w1], v1x, dummy);
        unpack2(s1y[w1], v1y, dummy);
        unpack2(s1z[w1], v1z, dummy);
        float4 v2 = g_pts[c2 * PTS_PER + w2];

        float dx = v1x - v2.x;
        float dy = v1y - v2.y;
        float dz = v1z - v2.z;
        float lend = sqrtf(fmaf(dz, dz, fmaf(dy, dy, dx * dx)));
        float nx, ny, nz;
        if (lend > 0.0f) {
            nx = dx / lend; ny = dy / lend; nz = dz / lend;
        } else {
            nx = dx; ny = dy; nz = dz;
        }

        float B[9];
        B[0] = nx * nx; B[1] = nx * ny; B[2] = nx * nz;
        B[3] = ny * nx; B[4] = ny * ny; B[5] = ny * nz;
        B[6] = nz * nx; B[7] = nz * ny; B[8] = nz * nz;

        float* o1 = out + (size_t)e * 38;
        float* o2 = o1 + 19;

        o1[0] = v1x;  o1[1] = v1y;  o1[2] = v1z;
        o1[3] = v2.x; o1[4] = v2.y; o1[5] = v2.z;
        o1[6] = nx;   o1[7] = ny;   o1[8] = nz;
        o1[9] = lend;
#pragma unroll
        for (int q = 0; q < 9; q++) o1[10 + q] = B[q];

        o2[0] = v2.x; o2[1] = v2.y; o2[2] = v2.z;
        o2[3] = v1x;  o2[4] = v1y;  o2[5] = v1z;
        o2[6] = -nx;  o2[7] = -ny;  o2[8] = -nz;
        o2[9] = lend;
#pragma unroll
        for (int q = 0; q < 9; q++) o2[10 + q] = B[q];
    }
}

// -------------------------------------------------------------------------
extern "C" void kernel_launch(void* const* d_in, const int* in_sizes, int n_in,
                              void* d_out, int out_size) {
    const float* data       = (const float*)d_in[0];   // [200000, 5] f32
    const int*   clusts     = (const int*)d_in[1];     // [1024, 128] i32
    const int*   edge_index = (const int*)d_in[2];     // [2, 8192] i32
    float*       out        = (float*)d_out;           // [16384, 19] f32

    gather_pts_kernel<<<(N_CLUSTS * PTS_PER + 255) / 256, 256>>>(data, clusts);
    edge_feats_kernel<<<N_EDGES, 256>>>(edge_index, out);
}

// round 6
// speedup vs baseline: 1.5024x; 1.1421x over previous
#include <cuda_runtime.h>
#include <stdint.h>

#define N_VOX        200000
#define N_COLS       5
#define N_CLUSTS     1024
#define PTS_PER      128
#define N_EDGES      8192

// Scratch: gathered cluster points, padded to float4.
__device__ float4 g_pts[N_CLUSTS * PTS_PER];

typedef unsigned long long ull;

// ---- packed f32x2 helpers (sm_103a FFMA2 path, PTX-only) ----
__device__ __forceinline__ ull pack2(float lo, float hi) {
    ull r; asm("mov.b64 %0, {%1,%2};" : "=l"(r) : "f"(lo), "f"(hi)); return r;
}
__device__ __forceinline__ void unpack2(ull v, float& lo, float& hi) {
    asm("mov.b64 {%0,%1}, %2;" : "=f"(lo), "=f"(hi) : "l"(v));
}
__device__ __forceinline__ ull add2(ull a, ull b) {
    ull r; asm("add.rn.f32x2 %0, %1, %2;" : "=l"(r) : "l"(a), "l"(b)); return r;
}
__device__ __forceinline__ ull mul2(ull a, ull b) {
    ull r; asm("mul.rn.f32x2 %0, %1, %2;" : "=l"(r) : "l"(a), "l"(b)); return r;
}
__device__ __forceinline__ ull fma2(ull a, ull b, ull c) {
    ull r; asm("fma.rn.f32x2 %0, %1, %2, %3;" : "=l"(r) : "l"(a), "l"(b), "l"(c)); return r;
}

// -------------------------------------------------------------------------
// Kernel 1: gather voxels[clusts] -> g_pts
// -------------------------------------------------------------------------
__global__ void gather_pts_kernel(const float* __restrict__ data,
                                  const int* __restrict__ clusts) {
    int i = blockIdx.x * blockDim.x + threadIdx.x;
    if (i >= N_CLUSTS * PTS_PER) return;
    int idx = clusts[i];
    const float* p = data + (size_t)idx * N_COLS + 1;
    g_pts[i] = make_float4(p[0], p[1], p[2], 0.0f);
}

// -------------------------------------------------------------------------
// Kernel 2: one CTA (128 threads) per edge.
// Thread (ti, tj): ti = t>>4 (0..7) owns i1 rows [16*ti, 16*ti+16);
//                  tj = t&15 owns i2 packs k = tj + 16*b (b=0..3),
//                  pack k = points {2k, 2k+1}  -> 8 i2 points / thread.
// => 128 pairs per thread; 128 threads cover 128x128.
// s1 coords stored DUPLICATE-PACKED (x,x); s2 coords NEGATED-PACKED so
// dx = x1 + s2 is a single ADD2.
// -------------------------------------------------------------------------
__global__ __launch_bounds__(128, 8)
void edge_feats_kernel(const int* __restrict__ edge_index,
                       float* __restrict__ out) {
    __shared__ ull s1x[PTS_PER], s1y[PTS_PER], s1z[PTS_PER];
    __shared__ ull s2x[64], s2y[64], s2z[64];
    __shared__ ull s_best;

    const int e = blockIdx.x;
    const int t = threadIdx.x;

    const int c1 = edge_index[e];
    const int c2 = edge_index[N_EDGES + e];

    if (t == 0) s_best = 0xFFFFFFFFFFFFFFFFull;

    {
        float4 p = g_pts[c1 * PTS_PER + t];
        s1x[t] = pack2(p.x, p.x);
        s1y[t] = pack2(p.y, p.y);
        s1z[t] = pack2(p.z, p.z);
        if (t < 64) {
            float4 a = g_pts[c2 * PTS_PER + 2 * t];
            float4 b = g_pts[c2 * PTS_PER + 2 * t + 1];
            s2x[t] = pack2(-a.x, -b.x);
            s2y[t] = pack2(-a.y, -b.y);
            s2z[t] = pack2(-a.z, -b.z);
        }
    }
    __syncthreads();

    const int ti = t >> 4;
    const int tj = t & 15;
    const int i1base = ti * 16;

    // Hoist this thread's 4 negated-v2 packs (conflict-free LDS.64).
    ull vx[4], vy[4], vz[4];
#pragma unroll
    for (int b = 0; b < 4; b++) {
        vx[b] = s2x[tj + 16 * b];
        vy[b] = s2y[tj + 16 * b];
        vz[b] = s2z[tj + 16 * b];
    }

    float bd = __int_as_float(0x7F800000);   // +inf
    int besta = 0;

    // ---- hot loop: 16 rows, distances + row-min only (no index tracking) ----
#pragma unroll
    for (int a = 0; a < 16; a++) {
        ull px = s1x[i1base + a];
        ull py = s1y[i1base + a];
        ull pz = s1z[i1base + a];

        float h[8];
#pragma unroll
        for (int b = 0; b < 4; b++) {
            ull dx = add2(px, vx[b]);
            ull dy = add2(py, vy[b]);
            ull dz = add2(pz, vz[b]);
            ull d2 = fma2(dz, dz, fma2(dy, dy, mul2(dx, dx)));
            unpack2(d2, h[2 * b], h[2 * b + 1]);
        }

        float m01 = fminf(h[0], h[1]);
        float m23 = fminf(h[2], h[3]);
        float m45 = fminf(h[4], h[5]);
        float m67 = fminf(h[6], h[7]);
        float m = fminf(fminf(m01, m23), fminf(m45, m67));

        // Last strict improvement == first row attaining the final min.
        bool imp = (m < bd);
        bd = imp ? m : bd;
        besta = imp ? a : besta;
    }

    // ---- one-shot index recovery: recompute row `besta` (identical math) ----
    {
        ull px = s1x[i1base + besta];
        ull py = s1y[i1base + besta];
        ull pz = s1z[i1base + besta];

        float h[8];
#pragma unroll
        for (int b = 0; b < 4; b++) {
            ull dx = add2(px, vx[b]);
            ull dy = add2(py, vy[b]);
            ull dz = add2(pz, vz[b]);
            ull d2 = fma2(dz, dz, fma2(dy, dy, mul2(dx, dx)));
            unpack2(d2, h[2 * b], h[2 * b + 1]);
        }

        float cur = __int_as_float(0x7F800000);
        int bidx = 0;
        const int rowbase = (i1base + besta) * PTS_PER + 2 * tj;
#pragma unroll
        for (int q = 0; q < 8; q++) {
            int flat = rowbase + 32 * (q >> 1) + (q & 1);
            if (h[q] < cur) { cur = h[q]; bidx = flat; }   // ascending flat, strict <
        }

        // Pack (d2, flat): uint64 min == lexicographic min (d2 >= 0).
        ull key = ((ull)__float_as_uint(cur) << 32) | (unsigned int)bidx;

#pragma unroll
        for (int off = 16; off > 0; off >>= 1) {
            ull o = __shfl_down_sync(0xFFFFFFFFu, key, off);
            key = (o < key) ? o : key;
        }
        if ((t & 31) == 0) atomicMin(&s_best, key);
    }
    __syncthreads();

    if (t == 0) {
        ull k = s_best;
        int f  = (int)(k & 0xFFFFFFFFu);
        int w1 = f >> 7;
        int w2 = f & 127;

        float v1x, v1y, v1z, dummy;
        unpack2(s1x[w1], v1x, dummy);
        unpack2(s1y[w1], v1y, dummy);
        unpack2(s1z[w1], v1z, dummy);
        float4 v2 = g_pts[c2 * PTS_PER + w2];

        float dx = v1x - v2.x;
        float dy = v1y - v2.y;
        float dz = v1z - v2.z;
        float lend = sqrtf(fmaf(dz, dz, fmaf(dy, dy, dx * dx)));
        float nx, ny, nz;
        if (lend > 0.0f) {
            nx = dx / lend; ny = dy / lend; nz = dz / lend;
        } else {
            nx = dx; ny = dy; nz = dz;
        }

        float B[9];
        B[0] = nx * nx; B[1] = nx * ny; B[2] = nx * nz;
        B[3] = ny * nx; B[4] = ny * ny; B[5] = ny * nz;
        B[6] = nz * nx; B[7] = nz * ny; B[8] = nz * nz;

        float* o1 = out + (size_t)e * 38;
        float* o2 = o1 + 19;

        o1[0] = v1x;  o1[1] = v1y;  o1[2] = v1z;
        o1[3] = v2.x; o1[4] = v2.y; o1[5] = v2.z;
        o1[6] = nx;   o1[7] = ny;   o1[8] = nz;
        o1[9] = lend;
#pragma unroll
        for (int q = 0; q < 9; q++) o1[10 + q] = B[q];

        o2[0] = v2.x; o2[1] = v2.y; o2[2] = v2.z;
        o2[3] = v1x;  o2[4] = v1y;  o2[5] = v1z;
        o2[6] = -nx;  o2[7] = -ny;  o2[8] = -nz;
        o2[9] = lend;
#pragma unroll
        for (int q = 0; q < 9; q++) o2[10 + q] = B[q];
    }
}

// -------------------------------------------------------------------------
extern "C" void kernel_launch(void* const* d_in, const int* in_sizes, int n_in,
                              void* d_out, int out_size) {
    const float* data       = (const float*)d_in[0];   // [200000, 5] f32
    const int*   clusts     = (const int*)d_in[1];     // [1024, 128] i32
    const int*   edge_index = (const int*)d_in[2];     // [2, 8192] i32
    float*       out        = (float*)d_out;           // [16384, 19] f32

    gather_pts_kernel<<<(N_CLUSTS * PTS_PER + 255) / 256, 256>>>(data, clusts);
    edge_feats_kernel<<<N_EDGES, 128>>>(edge_index, out);
}